// round 1
// baseline (speedup 1.0000x reference)
#include <cuda_runtime.h>
#include <cuda_bf16.h>
#include <math.h>

// Problem constants (B=16, S=8192, D=192, H=16, HD=12, W=2)
constexpr int Bsz  = 16;
constexpr int Sln  = 8192;
constexpr int Dm   = 192;
constexpr int Mtot = Bsz * Sln;            // 131072 token rows
constexpr int Hn   = 16;
constexpr int HDm  = 12;
constexpr float NEGF = -3.402823466e+38f;  // finfo(float32).min

// Scratch (device globals; no runtime allocation)
__device__ float g_qkv[(size_t)Mtot * 576];   // [M, 576] = q(192) | k(192) | v(192)
__device__ float g_attn[(size_t)Mtot * 192];  // [M, 192]

// ---------------------------------------------------------------------------
// GEMM: out[m, colOff+n] = (sum_k A[m,k] * W[n,k] + bias[n]) * scale (+ resid)
// A: [M, 192] row-major, W: [192,192] row-major (output-feature rows)
// BM=128, BN=64, BK=16, 128 threads, 8x8 microtile, double-buffered.
// ---------------------------------------------------------------------------
constexpr int BM = 128, BN = 64, BK = 16;
constexpr int GK = 192, NCH = GK / BK;  // 12 k-chunks

__global__ void __launch_bounds__(128, 4) gemm192(
    const float* __restrict__ A, const float* __restrict__ W,
    const float* __restrict__ bias, const float* __restrict__ resid,
    float* __restrict__ out, int ldOut, int colOff, float scale)
{
    __shared__ float As[2][BK][BM + 4];   // [k][m], stride 132 (16B multiple)
    __shared__ float Bs[2][BK][BN + 4];   // [k][n], stride 68  (16B multiple)

    const int m0 = blockIdx.x * BM;
    const int n0 = blockIdx.y * BN;
    const int tid = threadIdx.x;
    const int tx = tid & 7;       // N-dir (8)
    const int ty = tid >> 3;      // M-dir (16)

    float4 aReg[4], bReg[2];

    auto loadGlobal = [&](int ch) {
        const int k0 = ch * BK;
        #pragma unroll
        for (int i = 0; i < 4; i++) {
            int id = tid + i * 128;
            int r = id >> 2, f = id & 3;
            aReg[i] = *(const float4*)(A + (size_t)(m0 + r) * GK + k0 + f * 4);
        }
        #pragma unroll
        for (int i = 0; i < 2; i++) {
            int id = tid + i * 128;
            int r = id >> 2, f = id & 3;
            bReg[i] = *(const float4*)(W + (size_t)(n0 + r) * GK + k0 + f * 4);
        }
    };
    auto storeSmem = [&](int buf) {
        #pragma unroll
        for (int i = 0; i < 4; i++) {
            int id = tid + i * 128;
            int r = id >> 2, f = id & 3;
            As[buf][f * 4 + 0][r] = aReg[i].x;
            As[buf][f * 4 + 1][r] = aReg[i].y;
            As[buf][f * 4 + 2][r] = aReg[i].z;
            As[buf][f * 4 + 3][r] = aReg[i].w;
        }
        #pragma unroll
        for (int i = 0; i < 2; i++) {
            int id = tid + i * 128;
            int r = id >> 2, f = id & 3;
            Bs[buf][f * 4 + 0][r] = bReg[i].x;
            Bs[buf][f * 4 + 1][r] = bReg[i].y;
            Bs[buf][f * 4 + 2][r] = bReg[i].z;
            Bs[buf][f * 4 + 3][r] = bReg[i].w;
        }
    };

    float acc[8][8];
    #pragma unroll
    for (int i = 0; i < 8; i++)
        #pragma unroll
        for (int j = 0; j < 8; j++) acc[i][j] = 0.f;

    loadGlobal(0);
    storeSmem(0);
    __syncthreads();

    for (int ch = 0; ch < NCH; ch++) {
        const int buf = ch & 1;
        if (ch + 1 < NCH) loadGlobal(ch + 1);
        #pragma unroll
        for (int kk = 0; kk < BK; kk++) {
            float4 a0 = *(const float4*)&As[buf][kk][ty * 8];
            float4 a1 = *(const float4*)&As[buf][kk][ty * 8 + 4];
            float4 b0 = *(const float4*)&Bs[buf][kk][tx * 4];
            float4 b1 = *(const float4*)&Bs[buf][kk][32 + tx * 4];
            float av[8] = {a0.x, a0.y, a0.z, a0.w, a1.x, a1.y, a1.z, a1.w};
            float bw[8] = {b0.x, b0.y, b0.z, b0.w, b1.x, b1.y, b1.z, b1.w};
            #pragma unroll
            for (int i = 0; i < 8; i++)
                #pragma unroll
                for (int j = 0; j < 8; j++)
                    acc[i][j] = fmaf(av[i], bw[j], acc[i][j]);
        }
        if (ch + 1 < NCH) storeSmem(buf ^ 1);
        __syncthreads();
    }

    // Epilogue
    #pragma unroll
    for (int i = 0; i < 8; i++) {
        const int m = m0 + ty * 8 + i;
        float* orow = out + (size_t)m * ldOut + colOff + n0;
        const float* rrow = resid ? (resid + (size_t)m * Dm + n0) : nullptr;
        #pragma unroll
        for (int hf = 0; hf < 2; hf++) {
            const int nc = hf * 32 + tx * 4;
            float4 bb = *(const float4*)(bias + n0 + nc);
            float4 v;
            v.x = (acc[i][hf * 4 + 0] + bb.x) * scale;
            v.y = (acc[i][hf * 4 + 1] + bb.y) * scale;
            v.z = (acc[i][hf * 4 + 2] + bb.z) * scale;
            v.w = (acc[i][hf * 4 + 3] + bb.w) * scale;
            if (rrow) {
                float4 rr = *(const float4*)(rrow + nc);
                v.x += rr.x; v.y += rr.y; v.z += rr.z; v.w += rr.w;
            }
            *(float4*)(orow + nc) = v;
        }
    }
}

// ---------------------------------------------------------------------------
// Banded attention: one thread per (token, head). Window d in [-2, 2].
// ---------------------------------------------------------------------------
__global__ void attn_band(const float* __restrict__ qkv,
                          const float* __restrict__ mask0,
                          float* __restrict__ attn)
{
    const int idx = blockIdx.x * blockDim.x + threadIdx.x;
    if (idx >= Mtot * Hn) return;
    const int m = idx >> 4;
    const int hh = idx & 15;
    const int s = m & (Sln - 1);

    const float4* qp = (const float4*)(qkv + (size_t)m * 576 + hh * 12);
    const float4 q0 = qp[0], q1 = qp[1], q2 = qp[2];

    float sc[5];
    #pragma unroll
    for (int d = 0; d < 5; d++) {
        const int off = d - 2;
        const unsigned sn = (unsigned)(s + off);
        if (sn < (unsigned)Sln) {
            const float4* kp = (const float4*)(qkv + (size_t)(m + off) * 576 + 192 + hh * 12);
            const float4 k0 = kp[0], k1 = kp[1], k2 = kp[2];
            float dot = q0.x * k0.x + q0.y * k0.y + q0.z * k0.z + q0.w * k0.w
                      + q1.x * k1.x + q1.y * k1.y + q1.z * k1.z + q1.w * k1.w
                      + q2.x * k2.x + q2.y * k2.y + q2.z * k2.z + q2.w * k2.w;
            const float mk = mask0[m + off];
            sc[d] = dot + (mk != 0.f ? NEGF : 0.f);
        } else {
            sc[d] = -INFINITY;
        }
    }

    float mx = sc[0];
    #pragma unroll
    for (int d = 1; d < 5; d++) mx = fmaxf(mx, sc[d]);
    float e[5], sum = 0.f;
    #pragma unroll
    for (int d = 0; d < 5; d++) { e[d] = expf(sc[d] - mx); sum += e[d]; }
    const float inv = 1.f / sum;
    const bool zeroed = (mask0[m] < 0.f);

    float4 c0 = {0, 0, 0, 0}, c1 = {0, 0, 0, 0}, c2 = {0, 0, 0, 0};
    #pragma unroll
    for (int d = 0; d < 5; d++) {
        const int off = d - 2;
        const unsigned sn = (unsigned)(s + off);
        if (sn < (unsigned)Sln) {
            const float p = zeroed ? 0.f : e[d] * inv;
            const float4* vp = (const float4*)(qkv + (size_t)(m + off) * 576 + 384 + hh * 12);
            const float4 v0 = vp[0], v1 = vp[1], v2 = vp[2];
            c0.x = fmaf(p, v0.x, c0.x); c0.y = fmaf(p, v0.y, c0.y);
            c0.z = fmaf(p, v0.z, c0.z); c0.w = fmaf(p, v0.w, c0.w);
            c1.x = fmaf(p, v1.x, c1.x); c1.y = fmaf(p, v1.y, c1.y);
            c1.z = fmaf(p, v1.z, c1.z); c1.w = fmaf(p, v1.w, c1.w);
            c2.x = fmaf(p, v2.x, c2.x); c2.y = fmaf(p, v2.y, c2.y);
            c2.z = fmaf(p, v2.z, c2.z); c2.w = fmaf(p, v2.w, c2.w);
        }
    }
    float4* op = (float4*)(attn + (size_t)m * 192 + hh * 12);
    op[0] = c0; op[1] = c1; op[2] = c2;
}

// ---------------------------------------------------------------------------
// LayerNorm over D=192, one warp per token, in-place on io.
// ---------------------------------------------------------------------------
__global__ void ln192(float* __restrict__ io,
                      const float* __restrict__ gamma,
                      const float* __restrict__ beta)
{
    const int w = (blockIdx.x * blockDim.x + threadIdx.x) >> 5;
    const int lane = threadIdx.x & 31;
    if (w >= Mtot) return;
    float* row = io + (size_t)w * 192;

    float v[6], s = 0.f, sq = 0.f;
    #pragma unroll
    for (int j = 0; j < 6; j++) {
        v[j] = row[lane + 32 * j];
        s += v[j];
        sq = fmaf(v[j], v[j], sq);
    }
    #pragma unroll
    for (int o = 16; o > 0; o >>= 1) {
        s  += __shfl_xor_sync(0xffffffffu, s, o);
        sq += __shfl_xor_sync(0xffffffffu, sq, o);
    }
    const float mu = s * (1.f / 192.f);
    const float var = sq * (1.f / 192.f) - mu * mu;
    const float r = rsqrtf(var + 1e-12f);
    #pragma unroll
    for (int j = 0; j < 6; j++) {
        const int c = lane + 32 * j;
        row[c] = (v[j] - mu) * r * gamma[c] + beta[c];
    }
}

// ---------------------------------------------------------------------------
extern "C" void kernel_launch(void* const* d_in, const int* in_sizes, int n_in,
                              void* d_out, int out_size)
{
    const float* x     = (const float*)d_in[0];
    const float* mask0 = (const float*)d_in[1];
    const float* Wq    = (const float*)d_in[2];
    const float* bq    = (const float*)d_in[3];
    const float* Wk    = (const float*)d_in[4];
    const float* bk    = (const float*)d_in[5];
    const float* Wv    = (const float*)d_in[6];
    const float* bv    = (const float*)d_in[7];
    const float* Wo    = (const float*)d_in[8];
    const float* bo    = (const float*)d_in[9];
    const float* ln_g  = (const float*)d_in[10];
    const float* ln_b  = (const float*)d_in[11];
    float* out = (float*)d_out;

    float *qkv, *attn;
    cudaGetSymbolAddress((void**)&qkv, g_qkv);
    cudaGetSymbolAddress((void**)&attn, g_attn);

    const float qscale = 1.0f / sqrtf((float)HDm);
    dim3 grid(Mtot / BM, Dm / BN);  // (1024, 3)

    gemm192<<<grid, 128>>>(x, Wq, bq, nullptr, qkv, 576, 0,   qscale);
    gemm192<<<grid, 128>>>(x, Wk, bk, nullptr, qkv, 576, 192, 1.0f);
    gemm192<<<grid, 128>>>(x, Wv, bv, nullptr, qkv, 576, 384, 1.0f);

    attn_band<<<(Mtot * Hn) / 256, 256>>>(qkv, mask0, attn);

    // O-projection + bias + residual -> d_out, then LayerNorm in place
    gemm192<<<grid, 128>>>(attn, Wo, bo, x, out, Dm, 0, 1.0f);
    ln192<<<(Mtot * 32) / 256, 256>>>(out, ln_g, ln_b);
}

// round 3
// speedup vs baseline: 1.0667x; 1.0667x over previous
#include <cuda_runtime.h>
#include <cuda_bf16.h>
#include <math.h>
#include <stdint.h>

// Problem constants (B=16, S=8192, D=192, H=16, HD=12, W=2)
constexpr int Bsz  = 16;
constexpr int Sln  = 8192;
constexpr int Dm   = 192;
constexpr int Mtot = Bsz * Sln;            // 131072 token rows
constexpr int Hn   = 16;
constexpr float NEGF = -3.402823466e+38f;  // finfo(float32).min
constexpr float QSCALE = 0.28867513459481287f; // 1/sqrt(12)

// ---------------------------------------------------------------------------
// Scratch (device globals; no runtime allocation)
// ---------------------------------------------------------------------------
__device__ __nv_bfloat16 g_asp[(size_t)Mtot * 384];     // x split: [M, hi192|lo192]
__device__ float         g_qkv[(size_t)Mtot * 576];     // q|k|v fp32
__device__ __nv_bfloat16 g_attn_sp[(size_t)Mtot * 384]; // attn out split
__device__ __nv_bfloat16 g_wsp[4 * 2 * 192 * 192];      // [w][hi/lo][N*K]
__device__ float         g_bias[768];                   // bq|bk|bv|bo

// ---------------------------------------------------------------------------
__device__ __forceinline__ uint32_t smem_to_u32(const void* p) {
    uint32_t a;
    asm("{ .reg .u64 t; cvta.to.shared.u64 t, %1; cvt.u32.u64 %0, t; }"
        : "=r"(a) : "l"(p));
    return a;
}
__device__ __forceinline__ void cpasync16(uint32_t dst, const void* src) {
    asm volatile("cp.async.cg.shared.global [%0], [%1], 16;" :: "r"(dst), "l"(src));
}
#define CP_COMMIT() asm volatile("cp.async.commit_group;" ::: "memory")
#define CP_WAIT2()  asm volatile("cp.async.wait_group 2;" ::: "memory")

#define LDSM_X4(f, addr)                                                        \
    asm volatile("ldmatrix.sync.aligned.m8n8.x4.shared.b16 {%0,%1,%2,%3}, [%4];"\
        : "=r"((f)[0]), "=r"((f)[1]), "=r"((f)[2]), "=r"((f)[3]) : "r"(addr))

#define MMA16816(d, a, b0v, b1v)                                                \
    asm volatile("mma.sync.aligned.m16n8k16.row.col.f32.bf16.bf16.f32 "         \
        "{%0,%1,%2,%3}, {%4,%5,%6,%7}, {%8,%9}, {%0,%1,%2,%3};"                 \
        : "+f"((d)[0]), "+f"((d)[1]), "+f"((d)[2]), "+f"((d)[3])                \
        : "r"((a)[0]), "r"((a)[1]), "r"((a)[2]), "r"((a)[3]), "r"(b0v), "r"(b1v))

// GEMM tiling
constexpr int ROWB  = 48;                 // smem row stride in bytes (24 bf16)
constexpr int ASZ   = 128 * ROWB;         // 6144 B per stage
constexpr int BSZ   = 192 * ROWB;         // 9216 B per stage
constexpr int STG   = ASZ + BSZ;          // 15360 B
constexpr int NSTG  = 4;
constexpr int SMEM_GEMM = NSTG * STG;     // 61440 B
constexpr int KSTEPS = 36;                // K=576 effective / 16

// ---------------------------------------------------------------------------
// Split x (fp32) -> [M, hi192 | lo192] bf16
// ---------------------------------------------------------------------------
__global__ void split_x(const float* __restrict__ x, __nv_bfloat16* __restrict__ dst) {
    const int id = blockIdx.x * blockDim.x + threadIdx.x;   // over M*48
    if (id >= Mtot * 48) return;
    const int m = id / 48, c = (id - m * 48) * 4;
    const float4 v = *(const float4*)(x + (size_t)m * 192 + c);
    __nv_bfloat16 h[4], l[4];
    const float vv[4] = {v.x, v.y, v.z, v.w};
    #pragma unroll
    for (int j = 0; j < 4; j++) {
        h[j] = __float2bfloat16_rn(vv[j]);
        l[j] = __float2bfloat16_rn(vv[j] - __bfloat162float(h[j]));
    }
    __nv_bfloat16* row = dst + (size_t)m * 384;
    *(__nv_bfloat162*)(row + c)       = __nv_bfloat162(h[0], h[1]);
    *(__nv_bfloat162*)(row + c + 2)   = __nv_bfloat162(h[2], h[3]);
    *(__nv_bfloat162*)(row + 192 + c) = __nv_bfloat162(l[0], l[1]);
    *(__nv_bfloat162*)(row + 194 + c) = __nv_bfloat162(l[2], l[3]);
}

// ---------------------------------------------------------------------------
// Split 4 weight matrices + gather biases
// ---------------------------------------------------------------------------
__global__ void split_wb(const float* __restrict__ Wq, const float* __restrict__ Wk,
                         const float* __restrict__ Wv, const float* __restrict__ Wo,
                         const float* __restrict__ bq, const float* __restrict__ bk,
                         const float* __restrict__ bv, const float* __restrict__ bo) {
    const int id = blockIdx.x * blockDim.x + threadIdx.x;
    const int NW = 192 * 192;
    if (id < 4 * NW) {
        const int w = id / NW, e = id - w * NW;
        const float* src = (w == 0) ? Wq : (w == 1) ? Wk : (w == 2) ? Wv : Wo;
        const float v = src[e];
        const __nv_bfloat16 h = __float2bfloat16_rn(v);
        g_wsp[(size_t)w * 2 * NW + e]      = h;
        g_wsp[(size_t)w * 2 * NW + NW + e] = __float2bfloat16_rn(v - __bfloat162float(h));
    } else {
        const int b = id - 4 * NW;
        if (b < 768) {
            const int w = b / 192, e = b - w * 192;
            g_bias[b] = (w == 0) ? bq[e] : (w == 1) ? bk[e] : (w == 2) ? bv[e] : bo[e];
        }
    }
}

// ---------------------------------------------------------------------------
// Tensor-core GEMM via mma.sync (bf16 hi/lo split, effective K=576):
//   out[m, colOff+n] = (sum_k A[m,k]*W[n,k] + bias[n]) * scale (+ resid)
// CTA tile 128x192, 256 threads (8 warps: 2M x 4N), 4-stage cp.async.
// ---------------------------------------------------------------------------
__global__ void __launch_bounds__(256, 1) gemm_tc(
    const __nv_bfloat16* __restrict__ Asp, int isQKV,
    const float* __restrict__ resid, float* __restrict__ out, int ldOut)
{
    extern __shared__ char smem[];
    const uint32_t sb = smem_to_u32(smem);
    const int tid  = threadIdx.x;
    const int wid  = tid >> 5, lane = tid & 31;
    const int wm   = wid >> 2;          // 0..1 (M half)
    const int wn   = wid & 3;           // 0..3 (N quarter)
    const int m0   = blockIdx.y * 128;
    const int w    = isQKV ? (int)blockIdx.x : 3;
    const int colOff = isQKV ? w * 192 : 0;
    const float scale = (isQKV && w == 0) ? QSCALE : 1.0f;
    const __nv_bfloat16* whi = g_wsp + (size_t)w * 2 * 36864;
    const __nv_bfloat16* wlo = whi + 36864;

    auto issueStage = [&](int s, int stage) {
        const int seg = s / 12, kk = s - seg * 12;
        const __nv_bfloat16* wseg = (seg == 2) ? wlo : whi;
        const int colA = (seg == 1 ? 192 : 0) + kk * 16;
        const int colB = kk * 16;
        const uint32_t aBase = sb + stage * STG;
        const uint32_t bBase = aBase + ASZ;
        {   // A: 128 rows x 2 chunks; thread -> (row = tid&127, chunk = tid>>7)
            const int r = tid & 127, c = tid >> 7;
            cpasync16(aBase + r * ROWB + c * 16,
                      Asp + (size_t)(m0 + r) * 384 + colA + c * 8);
        }
        #pragma unroll
        for (int j = tid; j < 384; j += 256) {  // B: 192 rows x 2 chunks
            const int c = j / 192, r = j - c * 192;
            cpasync16(bBase + r * ROWB + c * 16,
                      wseg + (size_t)r * 192 + colB + c * 8);
        }
        CP_COMMIT();
    };

    float acc[4][6][4];
    #pragma unroll
    for (int i = 0; i < 4; i++)
        #pragma unroll
        for (int j = 0; j < 6; j++)
            #pragma unroll
            for (int q = 0; q < 4; q++) acc[i][j][q] = 0.f;

    issueStage(0, 0);
    issueStage(1, 1);
    issueStage(2, 2);

    // Per-lane ldmatrix address components (within stage)
    const int lt = lane >> 3;           // tile index 0..3
    const int l7 = lane & 7;
    // A: r = wm*64 + mt*16 + (lt&1)*8 + l7, chunk = lt>>1
    const uint32_t aLane = (uint32_t)((wm * 64 + (lt & 1) * 8 + l7) * ROWB + (lt >> 1) * 16);
    // B: r = wn*48 + nt2*16 + (lt>>1)*8 + l7, chunk = lt&1
    const uint32_t bLane = (uint32_t)(ASZ + (wn * 48 + (lt >> 1) * 8 + l7) * ROWB + (lt & 1) * 16);

    for (int s = 0; s < KSTEPS; s++) {
        const int stage = s & 3;
        CP_WAIT2();
        __syncthreads();
        if (s + 3 < KSTEPS) issueStage(s + 3, (s + 3) & 3);

        const uint32_t stBase = sb + stage * STG;
        uint32_t af[4][4], bf[3][4];
        #pragma unroll
        for (int mt = 0; mt < 4; mt++)
            LDSM_X4(af[mt], stBase + aLane + mt * 16 * ROWB);
        #pragma unroll
        for (int nt2 = 0; nt2 < 3; nt2++)
            LDSM_X4(bf[nt2], stBase + bLane + nt2 * 16 * ROWB);

        #pragma unroll
        for (int mt = 0; mt < 4; mt++)
            #pragma unroll
            for (int nt = 0; nt < 6; nt++)
                MMA16816(acc[mt][nt], af[mt], bf[nt >> 1][(nt & 1) * 2], bf[nt >> 1][(nt & 1) * 2 + 1]);
    }

    // Epilogue: c0,c1 -> (m, n..n+1); c2,c3 -> (m+8, n..n+1)
    const int gi = lane >> 2, tg = lane & 3;
    const float* bias = g_bias + w * 192;
    #pragma unroll
    for (int mt = 0; mt < 4; mt++) {
        const int m = m0 + wm * 64 + mt * 16 + gi;
        #pragma unroll
        for (int nt = 0; nt < 6; nt++) {
            const int nb = wn * 48 + nt * 8 + tg * 2;
            const float2 bb = *(const float2*)(bias + nb);
            float2 v0, v1;
            v0.x = (acc[mt][nt][0] + bb.x) * scale;
            v0.y = (acc[mt][nt][1] + bb.y) * scale;
            v1.x = (acc[mt][nt][2] + bb.x) * scale;
            v1.y = (acc[mt][nt][3] + bb.y) * scale;
            if (resid) {
                const float2 r0 = *(const float2*)(resid + (size_t)m * 192 + nb);
                const float2 r1 = *(const float2*)(resid + (size_t)(m + 8) * 192 + nb);
                v0.x += r0.x; v0.y += r0.y; v1.x += r1.x; v1.y += r1.y;
            }
            *(float2*)(out + (size_t)m * ldOut + colOff + nb)       = v0;
            *(float2*)(out + (size_t)(m + 8) * ldOut + colOff + nb) = v1;
        }
    }
}

// ---------------------------------------------------------------------------
// Banded attention (thread per token-head), output split to bf16 hi/lo
// ---------------------------------------------------------------------------
__global__ void attn_band(const float* __restrict__ qkv,
                          const float* __restrict__ mask0,
                          __nv_bfloat16* __restrict__ attn_sp)
{
    const int idx = blockIdx.x * blockDim.x + threadIdx.x;
    if (idx >= Mtot * Hn) return;
    const int m = idx >> 4;
    const int hh = idx & 15;
    const int s = m & (Sln - 1);

    const float4* qp = (const float4*)(qkv + (size_t)m * 576 + hh * 12);
    const float4 q0 = qp[0], q1 = qp[1], q2 = qp[2];

    float sc[5];
    #pragma unroll
    for (int d = 0; d < 5; d++) {
        const int off = d - 2;
        if ((unsigned)(s + off) < (unsigned)Sln) {
            const float4* kp = (const float4*)(qkv + (size_t)(m + off) * 576 + 192 + hh * 12);
            const float4 k0 = kp[0], k1 = kp[1], k2 = kp[2];
            float dot = q0.x * k0.x + q0.y * k0.y + q0.z * k0.z + q0.w * k0.w
                      + q1.x * k1.x + q1.y * k1.y + q1.z * k1.z + q1.w * k1.w
                      + q2.x * k2.x + q2.y * k2.y + q2.z * k2.z + q2.w * k2.w;
            sc[d] = dot + (mask0[m + off] != 0.f ? NEGF : 0.f);
        } else {
            sc[d] = -INFINITY;
        }
    }
    float mx = sc[0];
    #pragma unroll
    for (int d = 1; d < 5; d++) mx = fmaxf(mx, sc[d]);
    float e[5], sum = 0.f;
    #pragma unroll
    for (int d = 0; d < 5; d++) { e[d] = expf(sc[d] - mx); sum += e[d]; }
    const float inv = 1.f / sum;
    const bool zeroed = (mask0[m] < 0.f);

    float c[12];
    #pragma unroll
    for (int j = 0; j < 12; j++) c[j] = 0.f;
    #pragma unroll
    for (int d = 0; d < 5; d++) {
        const int off = d - 2;
        if ((unsigned)(s + off) < (unsigned)Sln) {
            const float p = zeroed ? 0.f : e[d] * inv;
            const float4* vp = (const float4*)(qkv + (size_t)(m + off) * 576 + 384 + hh * 12);
            const float4 v0 = vp[0], v1 = vp[1], v2 = vp[2];
            c[0] = fmaf(p, v0.x, c[0]); c[1]  = fmaf(p, v0.y, c[1]);
            c[2] = fmaf(p, v0.z, c[2]); c[3]  = fmaf(p, v0.w, c[3]);
            c[4] = fmaf(p, v1.x, c[4]); c[5]  = fmaf(p, v1.y, c[5]);
            c[6] = fmaf(p, v1.z, c[6]); c[7]  = fmaf(p, v1.w, c[7]);
            c[8] = fmaf(p, v2.x, c[8]); c[9]  = fmaf(p, v2.y, c[9]);
            c[10] = fmaf(p, v2.z, c[10]); c[11] = fmaf(p, v2.w, c[11]);
        }
    }
    __nv_bfloat16* hi = attn_sp + (size_t)m * 384 + hh * 12;
    __nv_bfloat16* lo = hi + 192;
    #pragma unroll
    for (int j = 0; j < 6; j++) {
        const __nv_bfloat16 h0 = __float2bfloat16_rn(c[2 * j]);
        const __nv_bfloat16 h1 = __float2bfloat16_rn(c[2 * j + 1]);
        *(__nv_bfloat162*)(hi + 2 * j) = __nv_bfloat162(h0, h1);
        *(__nv_bfloat162*)(lo + 2 * j) = __nv_bfloat162(
            __float2bfloat16_rn(c[2 * j]     - __bfloat162float(h0)),
            __float2bfloat16_rn(c[2 * j + 1] - __bfloat162float(h1)));
    }
}

// ---------------------------------------------------------------------------
// LayerNorm over D=192, one warp per token, in-place
// ---------------------------------------------------------------------------
__global__ void ln192(float* __restrict__ io,
                      const float* __restrict__ gamma,
                      const float* __restrict__ beta)
{
    const int w = (blockIdx.x * blockDim.x + threadIdx.x) >> 5;
    const int lane = threadIdx.x & 31;
    if (w >= Mtot) return;
    float* row = io + (size_t)w * 192;

    float v[6], s = 0.f, sq = 0.f;
    #pragma unroll
    for (int j = 0; j < 6; j++) {
        v[j] = row[lane + 32 * j];
        s += v[j];
        sq = fmaf(v[j], v[j], sq);
    }
    #pragma unroll
    for (int o = 16; o > 0; o >>= 1) {
        s  += __shfl_xor_sync(0xffffffffu, s, o);
        sq += __shfl_xor_sync(0xffffffffu, sq, o);
    }
    const float mu = s * (1.f / 192.f);
    const float var = sq * (1.f / 192.f) - mu * mu;
    const float r = rsqrtf(var + 1e-12f);
    #pragma unroll
    for (int j = 0; j < 6; j++) {
        const int c = lane + 32 * j;
        row[c] = (v[j] - mu) * r * gamma[c] + beta[c];
    }
}

// ---------------------------------------------------------------------------
extern "C" void kernel_launch(void* const* d_in, const int* in_sizes, int n_in,
                              void* d_out, int out_size)
{
    const float* x     = (const float*)d_in[0];
    const float* mask0 = (const float*)d_in[1];
    const float* Wq    = (const float*)d_in[2];
    const float* bq    = (const float*)d_in[3];
    const float* Wk    = (const float*)d_in[4];
    const float* bk    = (const float*)d_in[5];
    const float* Wv    = (const float*)d_in[6];
    const float* bv    = (const float*)d_in[7];
    const float* Wo    = (const float*)d_in[8];
    const float* bo    = (const float*)d_in[9];
    const float* ln_g  = (const float*)d_in[10];
    const float* ln_b  = (const float*)d_in[11];
    float* out = (float*)d_out;

    __nv_bfloat16 *asp, *attn_sp;
    float *qkv;
    cudaGetSymbolAddress((void**)&asp, g_asp);
    cudaGetSymbolAddress((void**)&qkv, g_qkv);
    cudaGetSymbolAddress((void**)&attn_sp, g_attn_sp);

    cudaFuncSetAttribute(gemm_tc, cudaFuncAttributeMaxDynamicSharedMemorySize, SMEM_GEMM);

    split_x<<<(Mtot * 48) / 256, 256>>>(x, asp);
    split_wb<<<(4 * 192 * 192 + 768 + 255) / 256, 256>>>(Wq, Wk, Wv, Wo, bq, bk, bv, bo);

    // QKV: grid.x = weight (shares A tile in L2), grid.y = m tile
    gemm_tc<<<dim3(3, 1024), 256, SMEM_GEMM>>>(asp, 1, nullptr, qkv, 576);

    attn_band<<<(Mtot * Hn) / 256, 256>>>(qkv, mask0, attn_sp);

    // O projection + bias + residual -> d_out, then LayerNorm in place
    gemm_tc<<<dim3(1, 1024), 256, SMEM_GEMM>>>(attn_sp, 0, x, out, 192);

    ln192<<<(Mtot * 32) / 256, 256>>>(out, ln_g, ln_b);
}

// round 4
// speedup vs baseline: 1.3937x; 1.3065x over previous
#include <cuda_runtime.h>
#include <cuda_bf16.h>
#include <math.h>
#include <stdint.h>

// Problem constants (B=16, S=8192, D=192, H=16, HD=12, W=2)
constexpr int Bsz  = 16;
constexpr int Sln  = 8192;
constexpr int Dm   = 192;
constexpr int Mtot = Bsz * Sln;            // 131072 token rows
constexpr int Hn   = 16;
constexpr float NEGF = -3.402823466e+38f;  // finfo(float32).min
constexpr float QSCALE = 0.28867513459481287f; // 1/sqrt(12)

// ---------------------------------------------------------------------------
// Scratch (device globals; no runtime allocation)
// ---------------------------------------------------------------------------
__device__ __nv_bfloat16 g_asp[(size_t)Mtot * 384];     // x split: [M, hi192|lo192]
__device__ float         g_qkv[(size_t)Mtot * 576];     // q|k|v fp32
__device__ __nv_bfloat16 g_attn_sp[(size_t)Mtot * 384]; // attn out split
__device__ __nv_bfloat16 g_wsp[4 * 2 * 192 * 192];      // [w][hi/lo][N*K]
__device__ float         g_bias[768];                   // bq|bk|bv|bo

// ---------------------------------------------------------------------------
__device__ __forceinline__ uint32_t smem_to_u32(const void* p) {
    uint32_t a;
    asm("{ .reg .u64 t; cvta.to.shared.u64 t, %1; cvt.u32.u64 %0, t; }"
        : "=r"(a) : "l"(p));
    return a;
}
__device__ __forceinline__ void cpasync16(uint32_t dst, const void* src) {
    asm volatile("cp.async.cg.shared.global [%0], [%1], 16;" :: "r"(dst), "l"(src));
}
#define CP_COMMIT() asm volatile("cp.async.commit_group;" ::: "memory")
#define CP_WAIT2()  asm volatile("cp.async.wait_group 2;" ::: "memory")

#define LDSM_X4(f, addr)                                                        \
    asm volatile("ldmatrix.sync.aligned.m8n8.x4.shared.b16 {%0,%1,%2,%3}, [%4];"\
        : "=r"((f)[0]), "=r"((f)[1]), "=r"((f)[2]), "=r"((f)[3]) : "r"(addr))

#define MMA16816(d, a, b0v, b1v)                                                \
    asm volatile("mma.sync.aligned.m16n8k16.row.col.f32.bf16.bf16.f32 "         \
        "{%0,%1,%2,%3}, {%4,%5,%6,%7}, {%8,%9}, {%0,%1,%2,%3};"                 \
        : "+f"((d)[0]), "+f"((d)[1]), "+f"((d)[2]), "+f"((d)[3])                \
        : "r"((a)[0]), "r"((a)[1]), "r"((a)[2]), "r"((a)[3]), "r"(b0v), "r"(b1v))

// GEMM tiling: CTA 128x192, k-chunk 32, 4 stages
constexpr int ROWB  = 80;                 // smem row stride bytes (64B data + pad)
constexpr int ASZ   = 128 * ROWB;         // 10240 B
constexpr int BSZ   = 192 * ROWB;         // 15360 B
constexpr int STG   = ASZ + BSZ;          // 25600 B
constexpr int NSTG  = 4;
constexpr int SMEM_GEMM = NSTG * STG;     // 102400 B
constexpr int KSTEPS = 18;                // K=576 effective / 32

// ---------------------------------------------------------------------------
// Split x (fp32) -> [M, hi192 | lo192] bf16
// ---------------------------------------------------------------------------
__global__ void split_x(const float* __restrict__ x, __nv_bfloat16* __restrict__ dst) {
    const int id = blockIdx.x * blockDim.x + threadIdx.x;   // over M*48
    if (id >= Mtot * 48) return;
    const int m = id / 48, c = (id - m * 48) * 4;
    const float4 v = *(const float4*)(x + (size_t)m * 192 + c);
    __nv_bfloat16 h[4], l[4];
    const float vv[4] = {v.x, v.y, v.z, v.w};
    #pragma unroll
    for (int j = 0; j < 4; j++) {
        h[j] = __float2bfloat16_rn(vv[j]);
        l[j] = __float2bfloat16_rn(vv[j] - __bfloat162float(h[j]));
    }
    __nv_bfloat16* row = dst + (size_t)m * 384;
    *(__nv_bfloat162*)(row + c)       = __nv_bfloat162(h[0], h[1]);
    *(__nv_bfloat162*)(row + c + 2)   = __nv_bfloat162(h[2], h[3]);
    *(__nv_bfloat162*)(row + 192 + c) = __nv_bfloat162(l[0], l[1]);
    *(__nv_bfloat162*)(row + 194 + c) = __nv_bfloat162(l[2], l[3]);
}

// ---------------------------------------------------------------------------
// Split 4 weight matrices (Wq pre-scaled by 1/sqrt(HD)) + gather biases
// ---------------------------------------------------------------------------
__global__ void split_wb(const float* __restrict__ Wq, const float* __restrict__ Wk,
                         const float* __restrict__ Wv, const float* __restrict__ Wo,
                         const float* __restrict__ bq, const float* __restrict__ bk,
                         const float* __restrict__ bv, const float* __restrict__ bo) {
    const int id = blockIdx.x * blockDim.x + threadIdx.x;
    const int NW = 192 * 192;
    if (id < 4 * NW) {
        const int w = id / NW, e = id - w * NW;
        const float* src = (w == 0) ? Wq : (w == 1) ? Wk : (w == 2) ? Wv : Wo;
        float v = src[e];
        if (w == 0) v *= QSCALE;
        const __nv_bfloat16 h = __float2bfloat16_rn(v);
        g_wsp[(size_t)w * 2 * NW + e]      = h;
        g_wsp[(size_t)w * 2 * NW + NW + e] = __float2bfloat16_rn(v - __bfloat162float(h));
    } else {
        const int b = id - 4 * NW;
        if (b < 768) {
            const int w = b / 192, e = b - w * 192;
            const float bv_ = (w == 0) ? bq[e] * QSCALE
                           : (w == 1) ? bk[e] : (w == 2) ? bv[e] : bo[e];
            g_bias[b] = bv_;
        }
    }
}

// ---------------------------------------------------------------------------
// Tensor-core GEMM (bf16 hi/lo split, effective K=576):
//   out[m, colOff+n] = sum_k A[m,k]*W[n,k] + bias[n] (+ resid, + fused LN)
// CTA tile 128x192, 256 threads (8 warps: 2M x 4N), k-chunk 32, 4-stage.
// ---------------------------------------------------------------------------
__global__ void __launch_bounds__(256, 1) gemm_tc(
    const __nv_bfloat16* __restrict__ Asp, int isQKV,
    const float* __restrict__ resid, float* __restrict__ out, int ldOut,
    const float* __restrict__ gamma, const float* __restrict__ beta)
{
    extern __shared__ char smem[];
    const uint32_t sb = smem_to_u32(smem);
    const int tid  = threadIdx.x;
    const int wid  = tid >> 5, lane = tid & 31;
    const int wm   = wid >> 2;          // 0..1 (M half)
    const int wn   = wid & 3;           // 0..3 (N quarter)
    const int m0   = blockIdx.y * 128;
    const int w    = isQKV ? (int)blockIdx.x : 3;
    const int colOff = isQKV ? w * 192 : 0;
    const __nv_bfloat16* whi = g_wsp + (size_t)w * 2 * 36864;
    const __nv_bfloat16* wlo = whi + 36864;

    auto issueStage = [&](int s, int stage) {
        const int seg = s / 6, kk = s - seg * 6;
        const __nv_bfloat16* wseg = (seg == 2) ? wlo : whi;
        const int colA = (seg == 1 ? 192 : 0) + kk * 32;
        const int colB = kk * 32;
        const uint32_t aBase = sb + stage * STG;
        const uint32_t bBase = aBase + ASZ;
        #pragma unroll
        for (int i = 0; i < 2; i++) {            // A: 128 rows x 4 chunks
            const int id = tid + i * 256;
            const int r = id >> 2, c = id & 3;
            cpasync16(aBase + r * ROWB + c * 16,
                      Asp + (size_t)(m0 + r) * 384 + colA + c * 8);
        }
        #pragma unroll
        for (int i = 0; i < 3; i++) {            // B: 192 rows x 4 chunks
            const int id = tid + i * 256;
            const int r = id >> 2, c = id & 3;
            cpasync16(bBase + r * ROWB + c * 16,
                      wseg + (size_t)r * 192 + colB + c * 8);
        }
        CP_COMMIT();
    };

    float acc[4][6][4];
    #pragma unroll
    for (int i = 0; i < 4; i++)
        #pragma unroll
        for (int j = 0; j < 6; j++)
            #pragma unroll
            for (int q = 0; q < 4; q++) acc[i][j][q] = 0.f;

    issueStage(0, 0);
    issueStage(1, 1);
    issueStage(2, 2);

    const int lt = lane >> 3, l7 = lane & 7;
    const uint32_t aLane = (uint32_t)((wm * 64 + (lt & 1) * 8 + l7) * ROWB + (lt >> 1) * 16);
    const uint32_t bLane = (uint32_t)(ASZ + (wn * 48 + (lt >> 1) * 8 + l7) * ROWB + (lt & 1) * 16);

    for (int s = 0; s < KSTEPS; s++) {
        const int stage = s & 3;
        CP_WAIT2();
        __syncthreads();
        if (s + 3 < KSTEPS) issueStage(s + 3, (s + 3) & 3);
        else CP_COMMIT();   // keep group count aligned so wait_group 2 => stage s arrived

        const uint32_t stBase = sb + stage * STG;
        uint32_t af[4][2][4], bf[3][2][4];
        #pragma unroll
        for (int kh = 0; kh < 2; kh++) {
            #pragma unroll
            for (int mt = 0; mt < 4; mt++)
                LDSM_X4(af[mt][kh], stBase + aLane + mt * (16 * ROWB) + kh * 32);
            #pragma unroll
            for (int nt2 = 0; nt2 < 3; nt2++)
                LDSM_X4(bf[nt2][kh], stBase + bLane + nt2 * (16 * ROWB) + kh * 32);
        }
        #pragma unroll
        for (int kh = 0; kh < 2; kh++)
            #pragma unroll
            for (int mt = 0; mt < 4; mt++)
                #pragma unroll
                for (int nt = 0; nt < 6; nt++)
                    MMA16816(acc[mt][nt], af[mt][kh],
                             bf[nt >> 1][kh][(nt & 1) * 2], bf[nt >> 1][kh][(nt & 1) * 2 + 1]);
    }

    const int gi = lane >> 2, tg = lane & 3;
    const float* bias = g_bias + w * 192;

    if (!gamma) {
        // Plain epilogue (QKV): bias only
        #pragma unroll
        for (int mt = 0; mt < 4; mt++) {
            const int m = m0 + wm * 64 + mt * 16 + gi;
            #pragma unroll
            for (int nt = 0; nt < 6; nt++) {
                const int nb = wn * 48 + nt * 8 + tg * 2;
                const float2 bb = *(const float2*)(bias + nb);
                float2 v0, v1;
                v0.x = acc[mt][nt][0] + bb.x;  v0.y = acc[mt][nt][1] + bb.y;
                v1.x = acc[mt][nt][2] + bb.x;  v1.y = acc[mt][nt][3] + bb.y;
                *(float2*)(out + (size_t)m * ldOut + colOff + nb)       = v0;
                *(float2*)(out + (size_t)(m + 8) * ldOut + colOff + nb) = v1;
            }
        }
        return;
    }

    // Fused epilogue (O-projection): bias + residual + LayerNorm over N=192
    // 1) add bias + residual into acc
    #pragma unroll
    for (int mt = 0; mt < 4; mt++) {
        const int mA = m0 + wm * 64 + mt * 16 + gi;
        #pragma unroll
        for (int nt = 0; nt < 6; nt++) {
            const int nb = wn * 48 + nt * 8 + tg * 2;
            const float2 bb = *(const float2*)(bias + nb);
            const float2 r0 = *(const float2*)(resid + (size_t)mA * 192 + nb);
            const float2 r1 = *(const float2*)(resid + (size_t)(mA + 8) * 192 + nb);
            acc[mt][nt][0] += bb.x + r0.x;  acc[mt][nt][1] += bb.y + r0.y;
            acc[mt][nt][2] += bb.x + r1.x;  acc[mt][nt][3] += bb.y + r1.y;
        }
    }
    // 2) per-row partial sums over this warp's 48 columns
    float* sums = (float*)smem;           // [128][4]
    float* sqs  = sums + 512;             // [128][4]
    __syncthreads();                      // smem stages no longer needed
    #pragma unroll
    for (int mt = 0; mt < 4; mt++) {
        float sA = 0.f, qA = 0.f, sB = 0.f, qB = 0.f;
        #pragma unroll
        for (int nt = 0; nt < 6; nt++) {
            sA += acc[mt][nt][0] + acc[mt][nt][1];
            qA += acc[mt][nt][0] * acc[mt][nt][0] + acc[mt][nt][1] * acc[mt][nt][1];
            sB += acc[mt][nt][2] + acc[mt][nt][3];
            qB += acc[mt][nt][2] * acc[mt][nt][2] + acc[mt][nt][3] * acc[mt][nt][3];
        }
        #pragma unroll
        for (int o = 1; o <= 2; o <<= 1) {
            sA += __shfl_xor_sync(0xffffffffu, sA, o);
            qA += __shfl_xor_sync(0xffffffffu, qA, o);
            sB += __shfl_xor_sync(0xffffffffu, sB, o);
            qB += __shfl_xor_sync(0xffffffffu, qB, o);
        }
        if (tg == 0) {
            const int rA = wm * 64 + mt * 16 + gi;
            sums[rA * 4 + wn] = sA;  sqs[rA * 4 + wn] = qA;
            sums[(rA + 8) * 4 + wn] = sB;  sqs[(rA + 8) * 4 + wn] = qB;
        }
    }
    __syncthreads();
    // 3) normalize + write
    #pragma unroll
    for (int mt = 0; mt < 4; mt++) {
        const int rA = wm * 64 + mt * 16 + gi;
        const int mA = m0 + rA;
        const float sumA = sums[rA * 4] + sums[rA * 4 + 1] + sums[rA * 4 + 2] + sums[rA * 4 + 3];
        const float sqA  = sqs[rA * 4]  + sqs[rA * 4 + 1]  + sqs[rA * 4 + 2]  + sqs[rA * 4 + 3];
        const float sumB = sums[(rA + 8) * 4] + sums[(rA + 8) * 4 + 1] + sums[(rA + 8) * 4 + 2] + sums[(rA + 8) * 4 + 3];
        const float sqB  = sqs[(rA + 8) * 4]  + sqs[(rA + 8) * 4 + 1]  + sqs[(rA + 8) * 4 + 2]  + sqs[(rA + 8) * 4 + 3];
        const float muA = sumA * (1.f / 192.f);
        const float riA = rsqrtf(sqA * (1.f / 192.f) - muA * muA + 1e-12f);
        const float muB = sumB * (1.f / 192.f);
        const float riB = rsqrtf(sqB * (1.f / 192.f) - muB * muB + 1e-12f);
        #pragma unroll
        for (int nt = 0; nt < 6; nt++) {
            const int nb = wn * 48 + nt * 8 + tg * 2;
            const float2 gg = *(const float2*)(gamma + nb);
            const float2 be = *(const float2*)(beta + nb);
            float2 v0, v1;
            v0.x = (acc[mt][nt][0] - muA) * riA * gg.x + be.x;
            v0.y = (acc[mt][nt][1] - muA) * riA * gg.y + be.y;
            v1.x = (acc[mt][nt][2] - muB) * riB * gg.x + be.x;
            v1.y = (acc[mt][nt][3] - muB) * riB * gg.y + be.y;
            *(float2*)(out + (size_t)mA * 192 + nb)       = v0;
            *(float2*)(out + (size_t)(mA + 8) * 192 + nb) = v1;
        }
    }
}

// ---------------------------------------------------------------------------
// Banded attention (thread per token-head), output split to bf16 hi/lo
// ---------------------------------------------------------------------------
__global__ void attn_band(const float* __restrict__ qkv,
                          const float* __restrict__ mask0,
                          __nv_bfloat16* __restrict__ attn_sp)
{
    const int idx = blockIdx.x * blockDim.x + threadIdx.x;
    if (idx >= Mtot * Hn) return;
    const int m = idx >> 4;
    const int hh = idx & 15;
    const int s = m & (Sln - 1);

    const float4* qp = (const float4*)(qkv + (size_t)m * 576 + hh * 12);
    const float4 q0 = qp[0], q1 = qp[1], q2 = qp[2];

    float sc[5];
    #pragma unroll
    for (int d = 0; d < 5; d++) {
        const int off = d - 2;
        if ((unsigned)(s + off) < (unsigned)Sln) {
            const float4* kp = (const float4*)(qkv + (size_t)(m + off) * 576 + 192 + hh * 12);
            const float4 k0 = kp[0], k1 = kp[1], k2 = kp[2];
            float dot = q0.x * k0.x + q0.y * k0.y + q0.z * k0.z + q0.w * k0.w
                      + q1.x * k1.x + q1.y * k1.y + q1.z * k1.z + q1.w * k1.w
                      + q2.x * k2.x + q2.y * k2.y + q2.z * k2.z + q2.w * k2.w;
            sc[d] = dot + (mask0[m + off] != 0.f ? NEGF : 0.f);
        } else {
            sc[d] = -INFINITY;
        }
    }
    float mx = sc[0];
    #pragma unroll
    for (int d = 1; d < 5; d++) mx = fmaxf(mx, sc[d]);
    float e[5], sum = 0.f;
    #pragma unroll
    for (int d = 0; d < 5; d++) { e[d] = expf(sc[d] - mx); sum += e[d]; }
    const float inv = 1.f / sum;
    const bool zeroed = (mask0[m] < 0.f);

    float c[12];
    #pragma unroll
    for (int j = 0; j < 12; j++) c[j] = 0.f;
    #pragma unroll
    for (int d = 0; d < 5; d++) {
        const int off = d - 2;
        if ((unsigned)(s + off) < (unsigned)Sln) {
            const float p = zeroed ? 0.f : e[d] * inv;
            const float4* vp = (const float4*)(qkv + (size_t)(m + off) * 576 + 384 + hh * 12);
            const float4 v0 = vp[0], v1 = vp[1], v2 = vp[2];
            c[0] = fmaf(p, v0.x, c[0]); c[1]  = fmaf(p, v0.y, c[1]);
            c[2] = fmaf(p, v0.z, c[2]); c[3]  = fmaf(p, v0.w, c[3]);
            c[4] = fmaf(p, v1.x, c[4]); c[5]  = fmaf(p, v1.y, c[5]);
            c[6] = fmaf(p, v1.z, c[6]); c[7]  = fmaf(p, v1.w, c[7]);
            c[8] = fmaf(p, v2.x, c[8]); c[9]  = fmaf(p, v2.y, c[9]);
            c[10] = fmaf(p, v2.z, c[10]); c[11] = fmaf(p, v2.w, c[11]);
        }
    }
    __nv_bfloat16* hi = attn_sp + (size_t)m * 384 + hh * 12;
    __nv_bfloat16* lo = hi + 192;
    #pragma unroll
    for (int j = 0; j < 6; j++) {
        const __nv_bfloat16 h0 = __float2bfloat16_rn(c[2 * j]);
        const __nv_bfloat16 h1 = __float2bfloat16_rn(c[2 * j + 1]);
        *(__nv_bfloat162*)(hi + 2 * j) = __nv_bfloat162(h0, h1);
        *(__nv_bfloat162*)(lo + 2 * j) = __nv_bfloat162(
            __float2bfloat16_rn(c[2 * j]     - __bfloat162float(h0)),
            __float2bfloat16_rn(c[2 * j + 1] - __bfloat162float(h1)));
    }
}

// ---------------------------------------------------------------------------
extern "C" void kernel_launch(void* const* d_in, const int* in_sizes, int n_in,
                              void* d_out, int out_size)
{
    const float* x     = (const float*)d_in[0];
    const float* mask0 = (const float*)d_in[1];
    const float* Wq    = (const float*)d_in[2];
    const float* bq    = (const float*)d_in[3];
    const float* Wk    = (const float*)d_in[4];
    const float* bk    = (const float*)d_in[5];
    const float* Wv    = (const float*)d_in[6];
    const float* bv    = (const float*)d_in[7];
    const float* Wo    = (const float*)d_in[8];
    const float* bo    = (const float*)d_in[9];
    const float* ln_g  = (const float*)d_in[10];
    const float* ln_b  = (const float*)d_in[11];
    float* out = (float*)d_out;

    __nv_bfloat16 *asp, *attn_sp;
    float *qkv;
    cudaGetSymbolAddress((void**)&asp, g_asp);
    cudaGetSymbolAddress((void**)&qkv, g_qkv);
    cudaGetSymbolAddress((void**)&attn_sp, g_attn_sp);

    cudaFuncSetAttribute(gemm_tc, cudaFuncAttributeMaxDynamicSharedMemorySize, SMEM_GEMM);

    split_x<<<(Mtot * 48) / 256, 256>>>(x, asp);
    split_wb<<<(4 * 192 * 192 + 768 + 255) / 256, 256>>>(Wq, Wk, Wv, Wo, bq, bk, bv, bo);

    // QKV: grid.x = weight (shares A tile in L2), grid.y = m tile
    gemm_tc<<<dim3(3, 1024), 256, SMEM_GEMM>>>(asp, 1, nullptr, qkv, 576, nullptr, nullptr);

    attn_band<<<(Mtot * Hn) / 256, 256>>>(qkv, mask0, attn_sp);

    // O projection + bias + residual + fused LayerNorm -> d_out
    gemm_tc<<<dim3(1, 1024), 256, SMEM_GEMM>>>(attn_sp, 0, x, out, 192, ln_g, ln_b);
}

// round 5
// speedup vs baseline: 1.6899x; 1.2126x over previous
#include <cuda_runtime.h>
#include <cuda_bf16.h>
#include <math.h>
#include <stdint.h>

// Problem constants (B=16, S=8192, D=192, H=16, HD=12, W=2)
constexpr int Bsz  = 16;
constexpr int Sln  = 8192;
constexpr int Dm   = 192;
constexpr int Mtot = Bsz * Sln;            // 131072 token rows
constexpr int Hn   = 16;
constexpr float NEGF = -3.402823466e+38f;  // finfo(float32).min
constexpr float QSCALE = 0.28867513459481287f; // 1/sqrt(12)

// ---------------------------------------------------------------------------
// Scratch (device globals; no runtime allocation)
// ---------------------------------------------------------------------------
__device__ __nv_bfloat16 g_asp[(size_t)Mtot * 384];     // x split: [M, hi192|lo192]
__device__ float         g_qkv[(size_t)Mtot * 576];     // q|k|v fp32
__device__ __nv_bfloat16 g_attn_sp[(size_t)Mtot * 384]; // attn out split
__device__ __nv_bfloat16 g_wsp[4 * 2 * 192 * 192];      // [w][hi/lo][N*K]
__device__ float         g_bias[768];                   // bq|bk|bv|bo

// ---------------------------------------------------------------------------
__device__ __forceinline__ uint32_t smem_to_u32(const void* p) {
    uint32_t a;
    asm("{ .reg .u64 t; cvta.to.shared.u64 t, %1; cvt.u32.u64 %0, t; }"
        : "=r"(a) : "l"(p));
    return a;
}
__device__ __forceinline__ void cpasync16(uint32_t dst, const void* src) {
    asm volatile("cp.async.cg.shared.global [%0], [%1], 16;" :: "r"(dst), "l"(src));
}
#define CP_COMMIT() asm volatile("cp.async.commit_group;" ::: "memory")
#define CP_WAIT2()  asm volatile("cp.async.wait_group 2;" ::: "memory")

#define LDSM_X4(f, addr)                                                        \
    asm volatile("ldmatrix.sync.aligned.m8n8.x4.shared.b16 {%0,%1,%2,%3}, [%4];"\
        : "=r"((f)[0]), "=r"((f)[1]), "=r"((f)[2]), "=r"((f)[3]) : "r"(addr))

#define MMA16816(d, a, b0v, b1v)                                                \
    asm volatile("mma.sync.aligned.m16n8k16.row.col.f32.bf16.bf16.f32 "         \
        "{%0,%1,%2,%3}, {%4,%5,%6,%7}, {%8,%9}, {%0,%1,%2,%3};"                 \
        : "+f"((d)[0]), "+f"((d)[1]), "+f"((d)[2]), "+f"((d)[3])                \
        : "r"((a)[0]), "r"((a)[1]), "r"((a)[2]), "r"((a)[3]), "r"(b0v), "r"(b1v))

constexpr int ROWB   = 80;                // smem row stride bytes (64B data + pad)
constexpr int KSTEPS = 18;                // K=576 effective / 32

// QKV kernel: CTA 128x96, 2 CTAs/SM
constexpr int Q_ASZ = 128 * ROWB;         // 10240
constexpr int Q_BSZ = 96 * ROWB;          // 7680
constexpr int Q_STG = Q_ASZ + Q_BSZ;      // 17920
constexpr int SMEM_QKV = 4 * Q_STG;       // 71680

// O kernel: CTA 128x192, 512 threads, 1 CTA/SM
constexpr int O_ASZ = 128 * ROWB;         // 10240
constexpr int O_BSZ = 192 * ROWB;         // 15360
constexpr int O_STG = O_ASZ + O_BSZ;      // 25600
constexpr int SMEM_O = 4 * O_STG;         // 102400

// ---------------------------------------------------------------------------
// Split x (fp32) -> [M, hi192 | lo192] bf16
// ---------------------------------------------------------------------------
__global__ void split_x(const float* __restrict__ x, __nv_bfloat16* __restrict__ dst) {
    const int id = blockIdx.x * blockDim.x + threadIdx.x;   // over M*48
    if (id >= Mtot * 48) return;
    const int m = id / 48, c = (id - m * 48) * 4;
    const float4 v = *(const float4*)(x + (size_t)m * 192 + c);
    __nv_bfloat16 h[4], l[4];
    const float vv[4] = {v.x, v.y, v.z, v.w};
    #pragma unroll
    for (int j = 0; j < 4; j++) {
        h[j] = __float2bfloat16_rn(vv[j]);
        l[j] = __float2bfloat16_rn(vv[j] - __bfloat162float(h[j]));
    }
    __nv_bfloat16* row = dst + (size_t)m * 384;
    *(__nv_bfloat162*)(row + c)       = __nv_bfloat162(h[0], h[1]);
    *(__nv_bfloat162*)(row + c + 2)   = __nv_bfloat162(h[2], h[3]);
    *(__nv_bfloat162*)(row + 192 + c) = __nv_bfloat162(l[0], l[1]);
    *(__nv_bfloat162*)(row + 194 + c) = __nv_bfloat162(l[2], l[3]);
}

// ---------------------------------------------------------------------------
// Split 4 weight matrices (Wq pre-scaled by 1/sqrt(HD)) + gather biases
// ---------------------------------------------------------------------------
__global__ void split_wb(const float* __restrict__ Wq, const float* __restrict__ Wk,
                         const float* __restrict__ Wv, const float* __restrict__ Wo,
                         const float* __restrict__ bq, const float* __restrict__ bk,
                         const float* __restrict__ bv, const float* __restrict__ bo) {
    const int id = blockIdx.x * blockDim.x + threadIdx.x;
    const int NW = 192 * 192;
    if (id < 4 * NW) {
        const int w = id / NW, e = id - w * NW;
        const float* src = (w == 0) ? Wq : (w == 1) ? Wk : (w == 2) ? Wv : Wo;
        float v = src[e];
        if (w == 0) v *= QSCALE;
        const __nv_bfloat16 h = __float2bfloat16_rn(v);
        g_wsp[(size_t)w * 2 * NW + e]      = h;
        g_wsp[(size_t)w * 2 * NW + NW + e] = __float2bfloat16_rn(v - __bfloat162float(h));
    } else {
        const int b = id - 4 * NW;
        if (b < 768) {
            const int w = b / 192, e = b - w * 192;
            const float bv_ = (w == 0) ? bq[e] * QSCALE
                           : (w == 1) ? bk[e] : (w == 2) ? bv[e] : bo[e];
            g_bias[b] = bv_;
        }
    }
}

// ---------------------------------------------------------------------------
// QKV GEMM: CTA 128x96, 256 threads (8 warps: 4M x 2N), 2 CTAs/SM.
// grid = (6, Mtot/128): bx>>1 = weight, bx&1 = N half.
// ---------------------------------------------------------------------------
__global__ void __launch_bounds__(256, 2) gemm_qkv(
    const __nv_bfloat16* __restrict__ Asp, float* __restrict__ out)
{
    extern __shared__ char smem[];
    const uint32_t sb = smem_to_u32(smem);
    const int tid  = threadIdx.x;
    const int wid  = tid >> 5, lane = tid & 31;
    const int wm   = wid >> 1;          // 0..3 (32-row band)
    const int wn   = wid & 1;           // 0..1 (48-col band)
    const int m0   = blockIdx.y * 128;
    const int w    = blockIdx.x >> 1;
    const int n0   = (blockIdx.x & 1) * 96;
    const __nv_bfloat16* whi = g_wsp + (size_t)w * 2 * 36864;
    const __nv_bfloat16* wlo = whi + 36864;

    auto issueStage = [&](int s, int stage) {
        const int seg = s / 6, kk = s - seg * 6;
        const __nv_bfloat16* wseg = (seg == 2) ? wlo : whi;
        const int colA = (seg == 1 ? 192 : 0) + kk * 32;
        const int colB = kk * 32;
        const uint32_t aBase = sb + stage * Q_STG;
        const uint32_t bBase = aBase + Q_ASZ;
        #pragma unroll
        for (int i = 0; i < 2; i++) {            // A: 128 rows x 4 chunks = 512
            const int id = tid + i * 256;
            const int r = id >> 2, c = id & 3;
            cpasync16(aBase + r * ROWB + c * 16,
                      Asp + (size_t)(m0 + r) * 384 + colA + c * 8);
        }
        {   // B: 96 rows x 4 chunks = 384; half the threads do 2
            const int r = tid >> 2, c = tid & 3;
            if (r < 96)
                cpasync16(bBase + r * ROWB + c * 16,
                          wseg + (size_t)(n0 + r) * 192 + colB + c * 8);
            else {
                // ids 384..511 unused
            }
            const int id2 = tid + 256;
            const int r2 = id2 >> 2, c2 = id2 & 3;
            if (tid < 128)
                cpasync16(bBase + r2 * ROWB + c2 * 16,
                          wseg + (size_t)(n0 + r2) * 192 + colB + c2 * 8);
        }
        CP_COMMIT();
    };

    float acc[2][6][4];
    #pragma unroll
    for (int i = 0; i < 2; i++)
        #pragma unroll
        for (int j = 0; j < 6; j++)
            #pragma unroll
            for (int q = 0; q < 4; q++) acc[i][j][q] = 0.f;

    issueStage(0, 0);
    issueStage(1, 1);
    issueStage(2, 2);

    const int lt = lane >> 3, l7 = lane & 7;
    const uint32_t aLane = (uint32_t)((wm * 32 + (lt & 1) * 8 + l7) * ROWB + (lt >> 1) * 16);
    const uint32_t bLane = (uint32_t)(Q_ASZ + (wn * 48 + (lt >> 1) * 8 + l7) * ROWB + (lt & 1) * 16);

    for (int s = 0; s < KSTEPS; s++) {
        const int stage = s & 3;
        CP_WAIT2();
        __syncthreads();
        if (s + 3 < KSTEPS) issueStage(s + 3, (s + 3) & 3);
        else CP_COMMIT();   // keep group count aligned

        const uint32_t stBase = sb + stage * Q_STG;
        uint32_t af[2][2][4], bf[3][2][4];
        #pragma unroll
        for (int kh = 0; kh < 2; kh++) {
            #pragma unroll
            for (int mt = 0; mt < 2; mt++)
                LDSM_X4(af[mt][kh], stBase + aLane + mt * (16 * ROWB) + kh * 32);
            #pragma unroll
            for (int nt2 = 0; nt2 < 3; nt2++)
                LDSM_X4(bf[nt2][kh], stBase + bLane + nt2 * (16 * ROWB) + kh * 32);
        }
        #pragma unroll
        for (int kh = 0; kh < 2; kh++)
            #pragma unroll
            for (int mt = 0; mt < 2; mt++)
                #pragma unroll
                for (int nt = 0; nt < 6; nt++)
                    MMA16816(acc[mt][nt], af[mt][kh],
                             bf[nt >> 1][kh][(nt & 1) * 2], bf[nt >> 1][kh][(nt & 1) * 2 + 1]);
    }

    const int gi = lane >> 2, tg = lane & 3;
    const float* bias = g_bias + w * 192 + n0;
    #pragma unroll
    for (int mt = 0; mt < 2; mt++) {
        const int m = m0 + wm * 32 + mt * 16 + gi;
        #pragma unroll
        for (int nt = 0; nt < 6; nt++) {
            const int nb = wn * 48 + nt * 8 + tg * 2;
            const float2 bb = *(const float2*)(bias + nb);
            float2 v0, v1;
            v0.x = acc[mt][nt][0] + bb.x;  v0.y = acc[mt][nt][1] + bb.y;
            v1.x = acc[mt][nt][2] + bb.x;  v1.y = acc[mt][nt][3] + bb.y;
            *(float2*)(out + (size_t)m * 576 + w * 192 + n0 + nb)       = v0;
            *(float2*)(out + (size_t)(m + 8) * 576 + w * 192 + n0 + nb) = v1;
        }
    }
}

// ---------------------------------------------------------------------------
// O GEMM: CTA 128x192, 512 threads (16 warps: 4M x 4N), fused bias+resid+LN.
// ---------------------------------------------------------------------------
__global__ void __launch_bounds__(512, 1) gemm_o(
    const __nv_bfloat16* __restrict__ Asp,
    const float* __restrict__ resid, float* __restrict__ out,
    const float* __restrict__ gamma, const float* __restrict__ beta)
{
    extern __shared__ char smem[];
    const uint32_t sb = smem_to_u32(smem);
    const int tid  = threadIdx.x;
    const int wid  = tid >> 5, lane = tid & 31;
    const int wm   = wid >> 2;          // 0..3 (32-row band)
    const int wn   = wid & 3;           // 0..3 (48-col band)
    const int m0   = blockIdx.x * 128;
    const __nv_bfloat16* whi = g_wsp + (size_t)3 * 2 * 36864;
    const __nv_bfloat16* wlo = whi + 36864;

    auto issueStage = [&](int s, int stage) {
        const int seg = s / 6, kk = s - seg * 6;
        const __nv_bfloat16* wseg = (seg == 2) ? wlo : whi;
        const int colA = (seg == 1 ? 192 : 0) + kk * 32;
        const int colB = kk * 32;
        const uint32_t aBase = sb + stage * O_STG;
        const uint32_t bBase = aBase + O_ASZ;
        {   // A: 128 rows x 4 chunks = 512
            const int r = tid >> 2, c = tid & 3;
            cpasync16(aBase + r * ROWB + c * 16,
                      Asp + (size_t)(m0 + r) * 384 + colA + c * 8);
        }
        #pragma unroll
        for (int i = 0; i < 2; i++) {            // B: 192 rows x 4 chunks = 768
            const int id = tid + i * 512;
            const int r = id >> 2, c = id & 3;
            if (i == 0 || id < 768)
                cpasync16(bBase + r * ROWB + c * 16,
                          wseg + (size_t)r * 192 + colB + c * 8);
        }
        CP_COMMIT();
    };

    float acc[2][6][4];
    #pragma unroll
    for (int i = 0; i < 2; i++)
        #pragma unroll
        for (int j = 0; j < 6; j++)
            #pragma unroll
            for (int q = 0; q < 4; q++) acc[i][j][q] = 0.f;

    issueStage(0, 0);
    issueStage(1, 1);
    issueStage(2, 2);

    const int lt = lane >> 3, l7 = lane & 7;
    const uint32_t aLane = (uint32_t)((wm * 32 + (lt & 1) * 8 + l7) * ROWB + (lt >> 1) * 16);
    const uint32_t bLane = (uint32_t)(O_ASZ + (wn * 48 + (lt >> 1) * 8 + l7) * ROWB + (lt & 1) * 16);

    for (int s = 0; s < KSTEPS; s++) {
        const int stage = s & 3;
        CP_WAIT2();
        __syncthreads();
        if (s + 3 < KSTEPS) issueStage(s + 3, (s + 3) & 3);
        else CP_COMMIT();

        const uint32_t stBase = sb + stage * O_STG;
        uint32_t af[2][2][4], bf[3][2][4];
        #pragma unroll
        for (int kh = 0; kh < 2; kh++) {
            #pragma unroll
            for (int mt = 0; mt < 2; mt++)
                LDSM_X4(af[mt][kh], stBase + aLane + mt * (16 * ROWB) + kh * 32);
            #pragma unroll
            for (int nt2 = 0; nt2 < 3; nt2++)
                LDSM_X4(bf[nt2][kh], stBase + bLane + nt2 * (16 * ROWB) + kh * 32);
        }
        #pragma unroll
        for (int kh = 0; kh < 2; kh++)
            #pragma unroll
            for (int mt = 0; mt < 2; mt++)
                #pragma unroll
                for (int nt = 0; nt < 6; nt++)
                    MMA16816(acc[mt][nt], af[mt][kh],
                             bf[nt >> 1][kh][(nt & 1) * 2], bf[nt >> 1][kh][(nt & 1) * 2 + 1]);
    }

    const int gi = lane >> 2, tg = lane & 3;
    const float* bias = g_bias + 3 * 192;

    // bias + residual
    #pragma unroll
    for (int mt = 0; mt < 2; mt++) {
        const int mA = m0 + wm * 32 + mt * 16 + gi;
        #pragma unroll
        for (int nt = 0; nt < 6; nt++) {
            const int nb = wn * 48 + nt * 8 + tg * 2;
            const float2 bb = *(const float2*)(bias + nb);
            const float2 r0 = *(const float2*)(resid + (size_t)mA * 192 + nb);
            const float2 r1 = *(const float2*)(resid + (size_t)(mA + 8) * 192 + nb);
            acc[mt][nt][0] += bb.x + r0.x;  acc[mt][nt][1] += bb.y + r0.y;
            acc[mt][nt][2] += bb.x + r1.x;  acc[mt][nt][3] += bb.y + r1.y;
        }
    }
    // per-row partial sums across the 4 N-warps
    float* sums = (float*)smem;           // [128][4]
    float* sqs  = sums + 512;             // [128][4]
    __syncthreads();
    #pragma unroll
    for (int mt = 0; mt < 2; mt++) {
        float sA = 0.f, qA = 0.f, sB = 0.f, qB = 0.f;
        #pragma unroll
        for (int nt = 0; nt < 6; nt++) {
            sA += acc[mt][nt][0] + acc[mt][nt][1];
            qA += acc[mt][nt][0] * acc[mt][nt][0] + acc[mt][nt][1] * acc[mt][nt][1];
            sB += acc[mt][nt][2] + acc[mt][nt][3];
            qB += acc[mt][nt][2] * acc[mt][nt][2] + acc[mt][nt][3] * acc[mt][nt][3];
        }
        #pragma unroll
        for (int o = 1; o <= 2; o <<= 1) {
            sA += __shfl_xor_sync(0xffffffffu, sA, o);
            qA += __shfl_xor_sync(0xffffffffu, qA, o);
            sB += __shfl_xor_sync(0xffffffffu, sB, o);
            qB += __shfl_xor_sync(0xffffffffu, qB, o);
        }
        if (tg == 0) {
            const int rA = wm * 32 + mt * 16 + gi;
            sums[rA * 4 + wn] = sA;  sqs[rA * 4 + wn] = qA;
            sums[(rA + 8) * 4 + wn] = sB;  sqs[(rA + 8) * 4 + wn] = qB;
        }
    }
    __syncthreads();
    // normalize + write
    #pragma unroll
    for (int mt = 0; mt < 2; mt++) {
        const int rA = wm * 32 + mt * 16 + gi;
        const int mA = m0 + rA;
        const float sumA = sums[rA * 4] + sums[rA * 4 + 1] + sums[rA * 4 + 2] + sums[rA * 4 + 3];
        const float sqA  = sqs[rA * 4]  + sqs[rA * 4 + 1]  + sqs[rA * 4 + 2]  + sqs[rA * 4 + 3];
        const float sumB = sums[(rA + 8) * 4] + sums[(rA + 8) * 4 + 1] + sums[(rA + 8) * 4 + 2] + sums[(rA + 8) * 4 + 3];
        const float sqB  = sqs[(rA + 8) * 4]  + sqs[(rA + 8) * 4 + 1]  + sqs[(rA + 8) * 4 + 2]  + sqs[(rA + 8) * 4 + 3];
        const float muA = sumA * (1.f / 192.f);
        const float riA = rsqrtf(sqA * (1.f / 192.f) - muA * muA + 1e-12f);
        const float muB = sumB * (1.f / 192.f);
        const float riB = rsqrtf(sqB * (1.f / 192.f) - muB * muB + 1e-12f);
        #pragma unroll
        for (int nt = 0; nt < 6; nt++) {
            const int nb = wn * 48 + nt * 8 + tg * 2;
            const float2 gg = *(const float2*)(gamma + nb);
            const float2 be = *(const float2*)(beta + nb);
            float2 v0, v1;
            v0.x = (acc[mt][nt][0] - muA) * riA * gg.x + be.x;
            v0.y = (acc[mt][nt][1] - muA) * riA * gg.y + be.y;
            v1.x = (acc[mt][nt][2] - muB) * riB * gg.x + be.x;
            v1.y = (acc[mt][nt][3] - muB) * riB * gg.y + be.y;
            *(float2*)(out + (size_t)mA * 192 + nb)       = v0;
            *(float2*)(out + (size_t)(mA + 8) * 192 + nb) = v1;
        }
    }
}

// ---------------------------------------------------------------------------
// Banded attention (thread per token-head), output split to bf16 hi/lo
// ---------------------------------------------------------------------------
__global__ void attn_band(const float* __restrict__ qkv,
                          const float* __restrict__ mask0,
                          __nv_bfloat16* __restrict__ attn_sp)
{
    const int idx = blockIdx.x * blockDim.x + threadIdx.x;
    if (idx >= Mtot * Hn) return;
    const int m = idx >> 4;
    const int hh = idx & 15;
    const int s = m & (Sln - 1);

    const float4* qp = (const float4*)(qkv + (size_t)m * 576 + hh * 12);
    const float4 q0 = qp[0], q1 = qp[1], q2 = qp[2];

    float sc[5];
    #pragma unroll
    for (int d = 0; d < 5; d++) {
        const int off = d - 2;
        if ((unsigned)(s + off) < (unsigned)Sln) {
            const float4* kp = (const float4*)(qkv + (size_t)(m + off) * 576 + 192 + hh * 12);
            const float4 k0 = kp[0], k1 = kp[1], k2 = kp[2];
            float dot = q0.x * k0.x + q0.y * k0.y + q0.z * k0.z + q0.w * k0.w
                      + q1.x * k1.x + q1.y * k1.y + q1.z * k1.z + q1.w * k1.w
                      + q2.x * k2.x + q2.y * k2.y + q2.z * k2.z + q2.w * k2.w;
            sc[d] = dot + (mask0[m + off] != 0.f ? NEGF : 0.f);
        } else {
            sc[d] = -INFINITY;
        }
    }
    float mx = sc[0];
    #pragma unroll
    for (int d = 1; d < 5; d++) mx = fmaxf(mx, sc[d]);
    float e[5], sum = 0.f;
    #pragma unroll
    for (int d = 0; d < 5; d++) { e[d] = expf(sc[d] - mx); sum += e[d]; }
    const float inv = 1.f / sum;
    const bool zeroed = (mask0[m] < 0.f);

    float c[12];
    #pragma unroll
    for (int j = 0; j < 12; j++) c[j] = 0.f;
    #pragma unroll
    for (int d = 0; d < 5; d++) {
        const int off = d - 2;
        if ((unsigned)(s + off) < (unsigned)Sln) {
            const float p = zeroed ? 0.f : e[d] * inv;
            const float4* vp = (const float4*)(qkv + (size_t)(m + off) * 576 + 384 + hh * 12);
            const float4 v0 = vp[0], v1 = vp[1], v2 = vp[2];
            c[0] = fmaf(p, v0.x, c[0]); c[1]  = fmaf(p, v0.y, c[1]);
            c[2] = fmaf(p, v0.z, c[2]); c[3]  = fmaf(p, v0.w, c[3]);
            c[4] = fmaf(p, v1.x, c[4]); c[5]  = fmaf(p, v1.y, c[5]);
            c[6] = fmaf(p, v1.z, c[6]); c[7]  = fmaf(p, v1.w, c[7]);
            c[8] = fmaf(p, v2.x, c[8]); c[9]  = fmaf(p, v2.y, c[9]);
            c[10] = fmaf(p, v2.z, c[10]); c[11] = fmaf(p, v2.w, c[11]);
        }
    }
    __nv_bfloat16* hi = attn_sp + (size_t)m * 384 + hh * 12;
    __nv_bfloat16* lo = hi + 192;
    #pragma unroll
    for (int j = 0; j < 6; j++) {
        const __nv_bfloat16 h0 = __float2bfloat16_rn(c[2 * j]);
        const __nv_bfloat16 h1 = __float2bfloat16_rn(c[2 * j + 1]);
        *(__nv_bfloat162*)(hi + 2 * j) = __nv_bfloat162(h0, h1);
        *(__nv_bfloat162*)(lo + 2 * j) = __nv_bfloat162(
            __float2bfloat16_rn(c[2 * j]     - __bfloat162float(h0)),
            __float2bfloat16_rn(c[2 * j + 1] - __bfloat162float(h1)));
    }
}

// ---------------------------------------------------------------------------
extern "C" void kernel_launch(void* const* d_in, const int* in_sizes, int n_in,
                              void* d_out, int out_size)
{
    const float* x     = (const float*)d_in[0];
    const float* mask0 = (const float*)d_in[1];
    const float* Wq    = (const float*)d_in[2];
    const float* bq    = (const float*)d_in[3];
    const float* Wk    = (const float*)d_in[4];
    const float* bk    = (const float*)d_in[5];
    const float* Wv    = (const float*)d_in[6];
    const float* bv    = (const float*)d_in[7];
    const float* Wo    = (const float*)d_in[8];
    const float* bo    = (const float*)d_in[9];
    const float* ln_g  = (const float*)d_in[10];
    const float* ln_b  = (const float*)d_in[11];
    float* out = (float*)d_out;

    __nv_bfloat16 *asp, *attn_sp;
    float *qkv;
    cudaGetSymbolAddress((void**)&asp, g_asp);
    cudaGetSymbolAddress((void**)&qkv, g_qkv);
    cudaGetSymbolAddress((void**)&attn_sp, g_attn_sp);

    cudaFuncSetAttribute(gemm_qkv, cudaFuncAttributeMaxDynamicSharedMemorySize, SMEM_QKV);
    cudaFuncSetAttribute(gemm_o,   cudaFuncAttributeMaxDynamicSharedMemorySize, SMEM_O);

    split_x<<<(Mtot * 48) / 256, 256>>>(x, asp);
    split_wb<<<(4 * 192 * 192 + 768 + 255) / 256, 256>>>(Wq, Wk, Wv, Wo, bq, bk, bv, bo);

    // QKV: grid.x = weight*2 + Nhalf (x-fastest shares A tile in L2)
    gemm_qkv<<<dim3(6, 1024), 256, SMEM_QKV>>>(asp, qkv);

    attn_band<<<(Mtot * Hn) / 256, 256>>>(qkv, mask0, attn_sp);

    // O projection + bias + residual + fused LayerNorm -> d_out
    gemm_o<<<1024, 512, SMEM_O>>>(attn_sp, x, out, ln_g, ln_b);
}